// round 16
// baseline (speedup 1.0000x reference)
#include <cuda_runtime.h>
#include <cuda_bf16.h>

// Per-species linear (X[n,64] . W[species[n],64,1]) + segment_sum over sorted
// structural_indices -> out[n_structures].
// R14: hybrid schedule. First ~94% of atoms: R10's balanced static chunk
// distribution (best measured: 78.3us, grid 2368, 8-atom batches, int32
// indexing). Last ~6%: shared pool of 16-atom chunks pulled via one global
// atomic counter -- kills end-of-kernel spread (the only static-schedule loss)
// while keeping total grabs small (~7.5K; R13's mistake was 256-atom chunks =
// 1.3 chunks/warp = worse imbalance than static). Chunks stay monotone per
// warp (static region precedes dynamic; counter increasing), so the sorted-run
// cur_key aggregation carries across phases unchanged.

#define WARPS_PER_BLOCK 8
#define THREADS_PER_BLOCK (WARPS_PER_BLOCK * 32)
#define N_SPECIES 8
#define D_VEC4 16          // 64 floats / 4
#define DYN_CHUNK 16       // atoms per stolen chunk (multiple of 8)

__device__ int g_chunk_counter;

__global__ __launch_bounds__(THREADS_PER_BLOCK)
void atomistic_kernel(const float4* __restrict__ X4,
                      const float*  __restrict__ W,
                      const int*    __restrict__ species,
                      const int*    __restrict__ struct_idx,
                      float*        __restrict__ out,
                      int n_atoms,
                      int chunks_base,   // static 8-atom chunks per warp (floor)
                      int chunks_rem,    // first chunks_rem warps get one extra
                      int dyn_start,     // first atom of the dynamic pool
                      int n_dyn_chunks)  // 16-atom chunks in the pool
{
    __shared__ float4 Wsh[N_SPECIES * D_VEC4];
    for (int i = threadIdx.x; i < N_SPECIES * D_VEC4; i += blockDim.x)
        Wsh[i] = reinterpret_cast<const float4*>(W)[i];
    __syncthreads();

    const int warp = blockIdx.x * WARPS_PER_BLOCK + (threadIdx.x >> 5);
    const int lane = threadIdx.x & 31;
    const int half = lane >> 4;                  // which 4-atom group of the batch
    const int sub  = lane & 15;                  // float4 column within the row
    const unsigned halfmask = 0xFFFFu << (half * 16);

    int   cur_key = -1;
    float acc0 = 0.0f, acc1 = 0.0f;

    // Flush the current segment for this half-warp (call half-converged).
    auto flush = [&]() {
        float t = acc0 + acc1;
        t += __shfl_xor_sync(halfmask, t, 8);
        t += __shfl_xor_sync(halfmask, t, 4);
        t += __shfl_xor_sync(halfmask, t, 2);
        t += __shfl_xor_sync(halfmask, t, 1);
        if (sub == 0 && cur_key >= 0)
            atomicAdd(out + cur_key, t);
    };
    // Process one atom with boundary check (slow path / tail).
    auto proc1 = [&](int k, int s, float4 x) {
        if (k != cur_key) {
            flush();
            cur_key = k; acc0 = 0.0f; acc1 = 0.0f;
        }
        const float4 w = Wsh[s * D_VEC4 + sub];
        acc0 = fmaf(x.x, w.x, acc0);
        acc1 = fmaf(x.y, w.y, acc1);
        acc0 = fmaf(x.z, w.z, acc0);
        acc1 = fmaf(x.w, w.w, acc1);
    };
    // One fully-loaded atom on the fast path.
    auto fma4 = [&](int s, const float4& x) {
        const float4 w = Wsh[s * D_VEC4 + sub];
        acc0 = fmaf(x.x, w.x, acc0);
        acc1 = fmaf(x.y, w.y, acc1);
        acc0 = fmaf(x.z, w.z, acc0);
        acc1 = fmaf(x.w, w.w, acc1);
    };
    // Run the 8-atom-batch mainloop over [start, end). start % 8 == 0.
    auto run_range = [&](int start, int end) {
        const int nbatch = (end - start) >> 3;
        const int a0 = start + half * 4;
        const float4* xp = X4 + (size_t)a0 * D_VEC4 + sub;
        const int*    kp = struct_idx + a0;
        const int*    sp = species + a0;

        for (int b = 0; b < nbatch; ++b) {
            const float4 x0 = __ldcs(xp);
            const float4 x1 = __ldcs(xp + 1 * D_VEC4);
            const float4 x2 = __ldcs(xp + 2 * D_VEC4);
            const float4 x3 = __ldcs(xp + 3 * D_VEC4);
            const int4 kv = *reinterpret_cast<const int4*>(kp);
            const int4 sv = *reinterpret_cast<const int4*>(sp);
            xp += 8 * D_VEC4;
            kp += 8;
            sp += 8;

            if (kv.x == cur_key && kv.w == cur_key) {
                fma4(sv.x, x0); fma4(sv.y, x1); fma4(sv.z, x2); fma4(sv.w, x3);
            } else {
                proc1(kv.x, sv.x, x0);
                proc1(kv.y, sv.y, x1);
                proc1(kv.z, sv.z, x2);
                proc1(kv.w, sv.w, x3);
            }
        }
        // Sub-8 tail: 2 atoms per step, halves interleave (keys monotone per half).
        for (int a = start + nbatch * 8 + half; a < end; a += 2) {
            const int k = struct_idx[a];
            const int s = species[a];
            const float4 x = __ldcs(&X4[(size_t)a * D_VEC4 + sub]);
            proc1(k, s, x);
        }
    };

    // ── Phase 1: static balanced schedule over [0, dyn_start) ──
    {
        const int my_chunks = chunks_base + (warp < chunks_rem);
        const int start = 8 * (warp * chunks_base +
                               (warp < chunks_rem ? warp : chunks_rem));
        int end = start + 8 * my_chunks;
        if (end > dyn_start) end = dyn_start;
        if (start < end)
            run_range(start, end);
    }

    // ── Phase 2: steal 16-atom chunks from the tail pool ──
    for (;;) {
        int c;
        if (lane == 0)
            c = atomicAdd(&g_chunk_counter, 1);
        c = __shfl_sync(0xFFFFFFFFu, c, 0);
        if (c >= n_dyn_chunks) break;

        const int start = dyn_start + c * DYN_CHUNK;
        int end = start + DYN_CHUNK;
        if (end > n_atoms) end = n_atoms;
        run_range(start, end);
    }

    // Final flush (all lanes converged here).
    flush();
}

extern "C" void kernel_launch(void* const* d_in, const int* in_sizes, int n_in,
                              void* d_out, int out_size)
{
    // Input order: X, W, central_species, structural_indices, n_structures
    const float* X  = (const float*)d_in[0];
    const float* W  = (const float*)d_in[1];
    const int*   sp = (const int*)  d_in[2];
    const int*   si = (const int*)  d_in[3];
    float* out = (float*)d_out;

    const int n_atoms = in_sizes[2];

    // Reset steal counter + zero output (both graph-capturable memset nodes).
    void* ctr_ptr = nullptr;
    cudaGetSymbolAddress(&ctr_ptr, g_chunk_counter);
    cudaMemsetAsync(ctr_ptr, 0, sizeof(int), 0);
    cudaMemsetAsync(d_out, 0, (size_t)out_size * sizeof(float), 0);

    // R10's proven launch shape: ~3.2 waves at 5 CTAs/SM residency.
    const int blocks = 2368;
    const int total_warps = blocks * WARPS_PER_BLOCK;   // 18944

    // Static region: first ~94% of atoms, 16-aligned (keeps every phase-1 and
    // phase-2 start a multiple of 8 -> int4 loads stay 16B-aligned).
    int dyn_start = (int)(((long long)n_atoms * 94) / 100) & ~15;
    if (dyn_start < 0) dyn_start = 0;
    const int n_dyn_chunks = (n_atoms - dyn_start + DYN_CHUNK - 1) / DYN_CHUNK;

    // Balanced distribution of static 8-atom chunks across warps.
    const int static_chunks = dyn_start >> 3;
    const int chunks_base   = static_chunks / total_warps;
    const int chunks_rem    = static_chunks % total_warps;

    atomistic_kernel<<<blocks, THREADS_PER_BLOCK>>>(
        (const float4*)X, W, sp, si, out, n_atoms,
        chunks_base, chunks_rem, dyn_start, n_dyn_chunks);
}

// round 17
// speedup vs baseline: 1.1986x; 1.1986x over previous
#include <cuda_runtime.h>
#include <cuda_bf16.h>

// Per-species linear (X[n,64] . W[species[n],64,1]) + segment_sum over sorted
// structural_indices -> out[n_structures].
// FINAL (= R10, best measured 78.3us, DRAM 83.5% / 6613 GB/s):
//  - 16 lanes per atom, float4 __ldcs streaming loads of X (528 MB, irreducible)
//  - W (2 KB) staged in shared
//  - 8-atom warp batches: 4 front-batched independent X loads + int4 key/species
//  - sorted-run fast path: whole batch in one segment -> straight FMAs;
//    per-lane accumulators persist across the segment, 16-lane shuffle
//    reduction + atomicAdd only at segment boundaries (~1/100 atoms)
//  - int32 indexing throughout (all indices < 2^31)
//  - grid 2368 (~3.2 waves @ 5 CTAs/SM), balanced 8-atom-chunk distribution.
// Scheduling experiments (single-wave equal-split, work-stealing, hybrid)
// all measured worse; static multi-wave balanced is the empirical optimum.

#define WARPS_PER_BLOCK 8
#define THREADS_PER_BLOCK (WARPS_PER_BLOCK * 32)
#define N_SPECIES 8
#define D_VEC4 16   // 64 floats / 4

__global__ __launch_bounds__(THREADS_PER_BLOCK)
void atomistic_kernel(const float4* __restrict__ X4,
                      const float*  __restrict__ W,
                      const int*    __restrict__ species,
                      const int*    __restrict__ struct_idx,
                      float*        __restrict__ out,
                      int n_atoms,
                      int chunks_base,   // 8-atom chunks per warp (floor)
                      int chunks_rem)    // first chunks_rem warps get one extra
{
    __shared__ float4 Wsh[N_SPECIES * D_VEC4];
    for (int i = threadIdx.x; i < N_SPECIES * D_VEC4; i += blockDim.x)
        Wsh[i] = reinterpret_cast<const float4*>(W)[i];
    __syncthreads();

    const int warp = blockIdx.x * WARPS_PER_BLOCK + (threadIdx.x >> 5);
    const int lane = threadIdx.x & 31;
    const int half = lane >> 4;                  // which 4-atom group of the batch
    const int sub  = lane & 15;                  // float4 column within the row
    const unsigned halfmask = 0xFFFFu << (half * 16);

    // Balanced distribution in units of 8-atom chunks (keeps the int4
    // key/species loads 16B-aligned). All arithmetic fits in int32:
    // n_atoms = 2e6, max element index 2e6*16 = 3.2e7 << 2^31.
    const int my_chunks = chunks_base + (warp < chunks_rem);
    const int start = 8 * (warp * chunks_base +
                           (warp < chunks_rem ? warp : chunks_rem));
    int end = start + 8 * my_chunks;
    if (end > n_atoms) end = n_atoms;
    if (start >= end) return;                    // uniform per warp

    const int nbatch = (end - start) >> 3;       // batches of 8 atoms

    int   cur_key = -1;
    float acc0 = 0.0f, acc1 = 0.0f;

    // Flush the current segment for this half-warp (call half-converged).
    auto flush = [&]() {
        float t = acc0 + acc1;
        t += __shfl_xor_sync(halfmask, t, 8);
        t += __shfl_xor_sync(halfmask, t, 4);
        t += __shfl_xor_sync(halfmask, t, 2);
        t += __shfl_xor_sync(halfmask, t, 1);
        if (sub == 0 && cur_key >= 0)
            atomicAdd(out + cur_key, t);
    };
    // Process one atom with boundary check (slow path / tail).
    auto proc1 = [&](int k, int s, float4 x) {
        if (k != cur_key) {
            flush();
            cur_key = k; acc0 = 0.0f; acc1 = 0.0f;
        }
        const float4 w = Wsh[s * D_VEC4 + sub];
        acc0 = fmaf(x.x, w.x, acc0);
        acc1 = fmaf(x.y, w.y, acc1);
        acc0 = fmaf(x.z, w.z, acc0);
        acc1 = fmaf(x.w, w.w, acc1);
    };
    // One fully-loaded atom on the fast path.
    auto fma4 = [&](int s, const float4& x) {
        const float4 w = Wsh[s * D_VEC4 + sub];
        acc0 = fmaf(x.x, w.x, acc0);
        acc1 = fmaf(x.y, w.y, acc1);
        acc0 = fmaf(x.z, w.z, acc0);
        acc1 = fmaf(x.w, w.w, acc1);
    };

    // Hot-loop pointers (this half's first atom is start + half*4).
    const int a0 = start + half * 4;
    const float4* xp = X4 + (size_t)a0 * D_VEC4 + sub;
    const int*    kp = struct_idx + a0;
    const int*    sp = species + a0;

    for (int b = 0; b < nbatch; ++b) {
        // Front-batched loads: 4 independent streaming float4s + vector keys.
        const float4 x0 = __ldcs(xp);
        const float4 x1 = __ldcs(xp + 1 * D_VEC4);
        const float4 x2 = __ldcs(xp + 2 * D_VEC4);
        const float4 x3 = __ldcs(xp + 3 * D_VEC4);
        const int4 kv = *reinterpret_cast<const int4*>(kp);
        const int4 sv = *reinterpret_cast<const int4*>(sp);
        xp += 8 * D_VEC4;   // 8 atoms forward (both halves)
        kp += 8;
        sp += 8;

        if (kv.x == cur_key && kv.w == cur_key) {
            // Sorted keys + first==last==cur -> all 4 atoms in current segment.
            fma4(sv.x, x0); fma4(sv.y, x1); fma4(sv.z, x2); fma4(sv.w, x3);
        } else {
            proc1(kv.x, sv.x, x0);
            proc1(kv.y, sv.y, x1);
            proc1(kv.z, sv.z, x2);
            proc1(kv.w, sv.w, x3);
        }
    }

    // Tail (< 8 atoms): 2 atoms per step, halves interleave; keys stay
    // monotone per half.
    for (int a = start + nbatch * 8 + half; a < end; a += 2) {
        const int k = struct_idx[a];
        const int s = species[a];
        const float4 x = __ldcs(&X4[(size_t)a * D_VEC4 + sub]);
        proc1(k, s, x);
    }

    // Final flush (all lanes converged here).
    flush();
}

extern "C" void kernel_launch(void* const* d_in, const int* in_sizes, int n_in,
                              void* d_out, int out_size)
{
    // Input order: X, W, central_species, structural_indices, n_structures
    const float* X  = (const float*)d_in[0];
    const float* W  = (const float*)d_in[1];
    const int*   sp = (const int*)  d_in[2];
    const int*   si = (const int*)  d_in[3];
    float* out = (float*)d_out;

    const int n_atoms = in_sizes[2];

    cudaMemsetAsync(d_out, 0, (size_t)out_size * sizeof(float), 0);

    // Best measured config: ~3.2 waves at 5 CTAs/SM residency, ~106 atoms/warp.
    const int blocks = 2368;
    const int total_warps = blocks * WARPS_PER_BLOCK;   // 18944

    // Balanced distribution of 8-atom chunks across warps.
    const int total_chunks = (n_atoms + 7) >> 3;        // 250000 for 2M atoms
    const int chunks_base  = total_chunks / total_warps;
    const int chunks_rem   = total_chunks % total_warps;

    atomistic_kernel<<<blocks, THREADS_PER_BLOCK>>>(
        (const float4*)X, W, sp, si, out, n_atoms, chunks_base, chunks_rem);
}